// round 13
// baseline (speedup 1.0000x reference)
#include <cuda_runtime.h>
#include <cuda_fp16.h>
#include <cstdint>

// ---------------------------------------------------------------------------
// SRNN text encoder:
//   1) X[b][t][4H] = emb[x[b,t]] @ Wih^T + (bih+bhh)   (fused dirs, fp32)
//   2) recurrence: 32 per-step HMMA kernels, cp.async 4-stage pipeline.
//      gates = X + h @ Whh^T via 3-term fp16 split (error ~2^-22), K=1536.
//      LSTM cell + cumsum fused in epilogue; h3 double-buffered by parity;
//      new chains read a permanently-zero pad row.
//   3) span means -> fp16 2-term split  A2[3968,2048]
//      Wout       -> fp16 2-term split  B2[7680,2048]
//   4) out = A2 @ B2^T + bout   via mma.sync fp16
// ---------------------------------------------------------------------------

#define NB    8
#define NT    32
#define HD    512
#define G4    2048
#define MROWS 3968
#define NOUT  7680
#define KC2   2048
#define KR3   1536
#define ZROW  260          // pad row in g_h3, never written => always zero

typedef unsigned long long ull;

__device__ float g_Xf[NB*NT*G4];
__device__ float g_Xb[NB*NT*G4];
__device__ float g_Af[NB*NT*NT*HD];
__device__ float g_Ab[NB*NT*NT*HD];
__device__ float g_Cf[NB*NT*HD];
__device__ float g_Cb[NB*NT*HD];
__device__ __half g_h3[2][2][264][KR3];      // [dir][buf][slot][k]
__device__ __half g_W3[2][2048][KR3];        // [dir][n=u*4+g][k]
__device__ __half g_Acat[(size_t)MROWS*KC2];
__device__ __half g_Bcat[(size_t)NOUT*KC2];

// ---- packed fp32 helpers ---------------------------------------------------
__device__ __forceinline__ void ffma2(ull &acc, ull a, ull b) {
    asm("fma.rn.f32x2 %0, %1, %2, %0;" : "+l"(acc) : "l"(a), "l"(b));
}
__device__ __forceinline__ ull pack2(float x, float y) {
    ull r; asm("mov.b64 %0, {%1, %2};" : "=l"(r) : "f"(x), "f"(y)); return r;
}
__device__ __forceinline__ float2 unpk(ull v) {
    float2 r; asm("mov.b64 {%0, %1}, %2;" : "=f"(r.x), "=f"(r.y) : "l"(v)); return r;
}

// ---- mma.sync / cp.async helpers ------------------------------------------
__device__ __forceinline__ void ldsm4(uint32_t &r0, uint32_t &r1, uint32_t &r2,
                                      uint32_t &r3, uint32_t saddr) {
    asm volatile("ldmatrix.sync.aligned.m8n8.x4.shared.b16 {%0,%1,%2,%3}, [%4];"
                 : "=r"(r0), "=r"(r1), "=r"(r2), "=r"(r3) : "r"(saddr));
}
__device__ __forceinline__ void mma16816(float* c, const uint32_t* a,
                                         uint32_t b0, uint32_t b1) {
    asm volatile("mma.sync.aligned.m16n8k16.row.col.f32.f16.f16.f32 "
                 "{%0,%1,%2,%3}, {%4,%5,%6,%7}, {%8,%9}, {%0,%1,%2,%3};"
                 : "+f"(c[0]), "+f"(c[1]), "+f"(c[2]), "+f"(c[3])
                 : "r"(a[0]), "r"(a[1]), "r"(a[2]), "r"(a[3]), "r"(b0), "r"(b1));
}
__device__ __forceinline__ void cpa16(uint32_t dst, const void* src) {
    asm volatile("cp.async.cg.shared.global [%0], [%1], 16;"
                 :: "r"(dst), "l"(src));
}
__device__ __forceinline__ void cpa_commit() {
    asm volatile("cp.async.commit_group;" ::: "memory");
}
template <int N>
__device__ __forceinline__ void cpa_wait() {
    asm volatile("cp.async.wait_group %0;" :: "n"(N) : "memory");
}
__device__ __forceinline__ void cpa_wait_all() {
    asm volatile("cp.async.wait_all;" ::: "memory");
}

// ---------------------------------------------------------------------------
// fused X precompute (both dirs via blockIdx.z), tile 64x128
// ---------------------------------------------------------------------------
__global__ __launch_bounds__(256)
void xgemm_kernel(const float* __restrict__ emb, const int* __restrict__ xidx,
                  const float* __restrict__ Wf, const float* __restrict__ Wb,
                  const float* __restrict__ b1f, const float* __restrict__ b2f,
                  const float* __restrict__ b1b, const float* __restrict__ b2b,
                  float* __restrict__ Cf, float* __restrict__ Cb)
{
    const int z = blockIdx.z;
    const float* Bm    = z ? Wb  : Wf;
    const float* bias1 = z ? b1b : b1f;
    const float* bias2 = z ? b2b : b2f;
    float*       C     = z ? Cb  : Cf;

    __shared__ float As[8][64];
    __shared__ float Bs[8][128];

    int tid = threadIdx.x;
    int tx = tid & 15, ty = tid >> 4;
    int m0 = blockIdx.y * 64, n0 = blockIdx.x * 128;

    ull acc[4][4];
#pragma unroll
    for (int i = 0; i < 4; i++)
#pragma unroll
        for (int j = 0; j < 4; j++) acc[i][j] = 0ull;

    for (int k0 = 0; k0 < 512; k0 += 8) {
        {
            int kk = tid & 7, row = tid >> 3;
            As[kk][row] = emb[(size_t)xidx[m0 + row] * 512 + k0 + kk];
            int e2 = 256 + tid;
            int kk2 = e2 & 7, row2 = e2 >> 3;
            As[kk2][row2] = emb[(size_t)xidx[m0 + row2] * 512 + k0 + kk2];
        }
#pragma unroll
        for (int r = 0; r < 4; r++) {
            int e = r * 256 + tid;
            int kk = e & 7, row = e >> 3;
            Bs[kk][row] = Bm[(size_t)(n0 + row) * 512 + k0 + kk];
        }
        __syncthreads();
#pragma unroll
        for (int kk = 0; kk < 8; kk++) {
            float4 a = *(const float4*)&As[kk][ty * 4];
            ulonglong2 b0 = *(const ulonglong2*)&Bs[kk][tx * 8];
            ulonglong2 b1 = *(const ulonglong2*)&Bs[kk][tx * 8 + 4];
            float av[4] = {a.x, a.y, a.z, a.w};
#pragma unroll
            for (int i = 0; i < 4; i++) {
                ull ad = pack2(av[i], av[i]);
                ffma2(acc[i][0], ad, b0.x); ffma2(acc[i][1], ad, b0.y);
                ffma2(acc[i][2], ad, b1.x); ffma2(acc[i][3], ad, b1.y);
            }
        }
        __syncthreads();
    }
#pragma unroll
    for (int i = 0; i < 4; i++) {
        float* crow = C + (size_t)(m0 + ty * 4 + i) * 2048 + n0 + tx * 8;
#pragma unroll
        for (int j2 = 0; j2 < 4; j2++) {
            float2 v = unpk(acc[i][j2]);
            int n = n0 + tx * 8 + j2 * 2;
            crow[j2 * 2]     = v.x + bias1[n] + bias2[n];
            crow[j2 * 2 + 1] = v.y + bias1[n + 1] + bias2[n + 1];
        }
    }
}

// ---------------------------------------------------------------------------
// Whh 3-term split, rows re-ordered unit-major: W3[dir][u*4+g] =
//   [wh | wl*2^11 | wh*2^-6]
// ---------------------------------------------------------------------------
__global__ __launch_bounds__(256)
void whh_split_kernel(const float* __restrict__ Wf, const float* __restrict__ Wb)
{
    int dir = blockIdx.y;
    int no = blockIdx.x;                 // original row g*512+u
    int g = no >> 9, u = no & 511;
    const float* src = (dir ? Wb : Wf) + (size_t)no * 512;
    __half* dst = g_W3[dir][u * 4 + g];
    for (int k = threadIdx.x; k < 512; k += 256) {
        float w = src[k];
        __half wh = __float2half(w);
        float whf = __half2float(wh);
        dst[k]        = wh;
        dst[512 + k]  = __float2half((w - whf) * 2048.0f);
        dst[1024 + k] = __float2half(whf * (1.0f / 64.0f));
    }
}

// ---------------------------------------------------------------------------
// One recurrence step, cp.async 4-stage pipelined HMMA.
// Tile 64 rows x 64 cols (=16 units), K=1536 in 48 chunks of 32.
// RSTR=40 halves (80 B): 16B-aligned rows for cp.async AND conflict-free
// ldmatrix ({r*80 mod 128} covers all eight 16B segments).
// ---------------------------------------------------------------------------
#define RSTR   40
#define NSTG   4
#define RCHUNK 48
#define ASTGH  (64 * RSTR)              // halves per A stage (2560)
#define STGH   (2 * ASTGH)              // A + B halves per stage (5120)

__global__ __launch_bounds__(256, 2)
void lstm_step_kernel(const float* __restrict__ Xf, const float* __restrict__ Xb,
                      int s)
{
    __shared__ __align__(16) char smbuf[NSTG * STGH * 2];   // 40960 B
    __shared__ int rowmap[64];          // slot*4 + nw*2 + active

    __half* stg  = (__half*)smbuf;
    float* gates = (float*)smbuf;       // overlay, used after K loop (64x68)
    (void)stg;

    const int dir = blockIdx.z;
    const int L = s + 1;
    const int Mact = 8 * L;
    const int t = dir ? (31 - s) : s;
    const int m0 = blockIdx.y * 64;
    const int n0 = blockIdx.x * 64;     // over 2048 (unit*4+gate)
    const int u0 = n0 >> 2;
    const int tid = threadIdx.x, wid = tid >> 5, lane = tid & 31;
    const int rb = s & 1, wb = rb ^ 1;

    if (tid < 64) {
        int r = m0 + tid;
        int v = 0;
        if (r < Mact) {
            int bb = r / L, j = r - bb * L;
            int slot = dir ? (bb * 32 + t + j) : (bb * 32 + j);
            int nw = dir ? (j == 0) : (j == s);
            v = slot * 4 + nw * 2 + 1;
        }
        rowmap[tid] = v;
    }
    __syncthreads();

    // staging: thread -> row tid>>2, 16B segment tid&3 (for both A and B)
    const int srow = tid >> 2, sseg = (tid & 3) * 8;
    int am = rowmap[srow];
    const __half* asrc = g_h3[dir][rb][(am & 2) || !(am & 1) ? ZROW : (am >> 2)]
                         + sseg;
    const __half* bsrc = g_W3[dir][n0 + srow] + sseg;
    const uint32_t sbase = (uint32_t)__cvta_generic_to_shared(smbuf);
    const uint32_t a_sm = sbase + (srow * RSTR + sseg) * 2;
    const uint32_t b_sm = sbase + (ASTGH + srow * RSTR + sseg) * 2;

    float acc[2][2][4];
#pragma unroll
    for (int i = 0; i < 2; i++)
#pragma unroll
        for (int j = 0; j < 2; j++)
#pragma unroll
            for (int r = 0; r < 4; r++) acc[i][j][r] = 0.f;

    const int wm = wid & 1, wn = wid >> 1;            // wn 0..3 (16 cols each)
    const int a_row = wm * 32 + (lane & 15);
    const int a_col = (lane >> 4) * 8;
    const int b_row = wn * 16 + ((lane >> 4) << 3) + (lane & 7);
    const int b_col = ((lane >> 3) & 1) * 8;

    // prologue: issue stages 0..2
#pragma unroll
    for (int p = 0; p < NSTG - 1; p++) {
        uint32_t so = (uint32_t)(p * STGH * 2);
        cpa16(a_sm + so, asrc + p * 32);
        cpa16(b_sm + so, bsrc + p * 32);
        cpa_commit();
    }

    for (int c = 0; c < RCHUNK; c++) {
        cpa_wait<2>();
        __syncthreads();
        if (c + NSTG - 1 < RCHUNK) {
            uint32_t so = (uint32_t)(((c + NSTG - 1) & (NSTG - 1)) * STGH * 2);
            cpa16(a_sm + so, asrc + (c + NSTG - 1) * 32);
            cpa16(b_sm + so, bsrc + (c + NSTG - 1) * 32);
        }
        cpa_commit();                    // may be empty (keeps group count uniform)

        const uint32_t abuf = sbase + (uint32_t)((c & (NSTG - 1)) * STGH * 2);
        const uint32_t bbuf = abuf + ASTGH * 2;
#pragma unroll
        for (int kb = 0; kb < 32; kb += 16) {
            uint32_t a[2][4], b[4];
#pragma unroll
            for (int i = 0; i < 2; i++)
                ldsm4(a[i][0], a[i][1], a[i][2], a[i][3],
                      abuf + ((a_row + i * 16) * RSTR + kb + a_col) * 2);
            ldsm4(b[0], b[1], b[2], b[3],
                  bbuf + (b_row * RSTR + kb + b_col) * 2);
#pragma unroll
            for (int i = 0; i < 2; i++) {
                mma16816(acc[i][0], a[i], b[0], b[1]);
                mma16816(acc[i][1], a[i], b[2], b[3]);
            }
        }
    }
    cpa_wait_all();
    __syncthreads();

    // acc -> gates overlay (row 0..63, col 0..63 = local unit*4+gate)
#pragma unroll
    for (int i = 0; i < 2; i++) {
        int row = wm * 32 + i * 16 + (lane >> 2);
#pragma unroll
        for (int jj = 0; jj < 2; jj++) {
            int col = wn * 16 + jj * 8 + (lane & 3) * 2;
            gates[row * 68 + col]           = acc[i][jj][0];
            gates[row * 68 + col + 1]       = acc[i][jj][1];
            gates[(row + 8) * 68 + col]     = acc[i][jj][2];
            gates[(row + 8) * 68 + col + 1] = acc[i][jj][3];
        }
    }
    __syncthreads();

    // LSTM cell: thread -> unit (tid&15), row group (tid>>4)*4
    const float* Xd = dir ? Xb : Xf;
    float* Cst = dir ? g_Cb : g_Cf;
    float* Ad  = dir ? g_Ab : g_Af;
    const int u = tid & 15, ug = u0 + u;
    const int rg = tid >> 4;
    const int tprev = dir ? (t + 1) : (t - 1);
#pragma unroll
    for (int rr = 0; rr < 4; rr++) {
        int r = rg * 4 + rr;
        int meta = rowmap[r];
        if (!(meta & 1)) continue;
        int slot = meta >> 2;
        bool nw = meta & 2;
        int bb = slot >> 5;
        float4 gv = *(const float4*)&gates[r * 68 + 4 * u];
        const float* Xrow = Xd + (size_t)(bb * 32 + t) * 2048;
        float gi = gv.x + Xrow[ug];
        float gf = gv.y + Xrow[512 + ug];
        float gg = gv.z + Xrow[1024 + ug];
        float go = gv.w + Xrow[1536 + ug];
        float cprev = nw ? 0.f : __ldcg(&Cst[slot * 512 + ug]);
        float ig = 1.f / (1.f + __expf(-gi));
        float fg = 1.f / (1.f + __expf(-gf));
        float og = 1.f / (1.f + __expf(-go));
        float gt = tanhf(gg);
        float cc = fg * cprev + ig * gt;
        float hh = og * tanhf(cc);
        Cst[slot * 512 + ug] = cc;
        float ap = nw ? 0.f : __ldcg(&Ad[((size_t)slot * 32 + tprev) * 512 + ug]);
        Ad[((size_t)slot * 32 + t) * 512 + ug] = ap + hh;
        __half hh16 = __float2half(hh);
        float hlf = hh - __half2float(hh16);
        __half* hrow = g_h3[dir][wb][slot];
        hrow[ug]        = hh16;
        hrow[512 + ug]  = __float2half(__half2float(hh16) * (1.0f / 2048.0f));
        hrow[1024 + ug] = __float2half(hlf * 64.0f);
    }
}

// ---------------------------------------------------------------------------
// span means -> fp16 2-term split:  A2 = [Mh | Mh*2^-11]
// ---------------------------------------------------------------------------
__global__ __launch_bounds__(256)
void mean_split_kernel()
{
    int sidx = blockIdx.x;
    int b = blockIdx.y;
    int k = 1, off = 0;
    while (off + (32 - k) <= sidx) { off += (32 - k); k++; }
    int p = sidx - off;
    int q = p + k;
    float inv = 1.f / (float)(k + 1);

    int tid = threadIdx.x;
    __half* dst = g_Acat + (size_t)(b * 496 + sidx) * KC2;
    const float* af = g_Af + (((size_t)(b * 32 + p)) * 32 + q) * 512;
    const float* ab = g_Ab + (((size_t)(b * 32 + q)) * 32 + p) * 512;
    const float s11 = 1.0f / 2048.0f;
    for (int uu = tid; uu < 512; uu += 256) {
        float f1 = af[uu] * inv;
        __half h1 = __float2half(f1);
        dst[uu]        = h1;
        dst[1024 + uu] = __float2half(__half2float(h1) * s11);
        float f2 = ab[uu] * inv;
        __half h2 = __float2half(f2);
        dst[512 + uu]  = h2;
        dst[1536 + uu] = __float2half(__half2float(h2) * s11);
    }
}

// ---------------------------------------------------------------------------
// Wout fp16 2-term split:  B2 = [Wh | (W - Wh)*2^11]
// ---------------------------------------------------------------------------
__global__ __launch_bounds__(256)
void wout_split_kernel(const float* __restrict__ Wout)
{
    int n = blockIdx.x;
    __half* dst = g_Bcat + (size_t)n * KC2;
    const float* src = Wout + (size_t)n * 1024;
    for (int k = threadIdx.x; k < 1024; k += 256) {
        float w = src[k];
        __half h = __float2half(w);
        dst[k]        = h;
        dst[1024 + k] = __float2half((w - __half2float(h)) * 2048.0f);
    }
}

// ---------------------------------------------------------------------------
// Projection via mma.sync (fp16, fp32 accum): out = A2 @ B2^T + bout
// ---------------------------------------------------------------------------
#define PSTRIDE 40
#define PCHUNK  32
#define NCHUNK  (KC2 / PCHUNK)   // 64

__global__ __launch_bounds__(256, 2)
void proj_mma_kernel(const float* __restrict__ bout, float* __restrict__ out)
{
    __shared__ __half As[2][128 * PSTRIDE];
    __shared__ __half Bs[2][128 * PSTRIDE];

    const int tid = threadIdx.x;
    const int wid = tid >> 5;
    const int lane = tid & 31;
    const int wm = wid & 1;
    const int wn = wid >> 1;
    const int m0 = blockIdx.y * 128;
    const int n0 = blockIdx.x * 128;

    const __half* Ag = g_Acat + (size_t)m0 * KC2;
    const __half* Bg = g_Bcat + (size_t)n0 * KC2;

    const int srow = tid >> 1;
    const int scol = (tid & 1) * 16;
    const __half* agp = Ag + (size_t)srow * KC2 + scol;
    const __half* bgp = Bg + (size_t)srow * KC2 + scol;
    const int ssoff = srow * PSTRIDE + scol;

    float acc[4][4][4];
#pragma unroll
    for (int i = 0; i < 4; i++)
#pragma unroll
        for (int j = 0; j < 4; j++)
#pragma unroll
            for (int r = 0; r < 4; r++) acc[i][j][r] = 0.f;

    uint32_t a_base = (uint32_t)__cvta_generic_to_shared(&As[0][0]);
    uint32_t b_base = (uint32_t)__cvta_generic_to_shared(&Bs[0][0]);
    const uint32_t bufA = 128 * PSTRIDE * 2;
    const int a_row = wm * 64 + (lane & 15);
    const int a_col = (lane >> 4) * 8;
    const int b_row = wn * 32 + ((lane >> 4) << 3) + (lane & 7);
    const int b_col = ((lane >> 3) & 1) * 8;

    {
        uint4 av0 = __ldg((const uint4*)(agp));
        uint4 av1 = __ldg((const uint4*)(agp + 8));
        uint4 bv0 = __ldg((const uint4*)(bgp));
        uint4 bv1 = __ldg((const uint4*)(bgp + 8));
        *(uint4*)&As[0][ssoff]     = av0;
        *(uint4*)&As[0][ssoff + 8] = av1;
        *(uint4*)&Bs[0][ssoff]     = bv0;
        *(uint4*)&Bs[0][ssoff + 8] = bv1;
    }
    __syncthreads();

    for (int c = 0; c < NCHUNK; c++) {
        const int cur = c & 1;
        uint4 av0, av1, bv0, bv1;
        if (c + 1 < NCHUNK) {
            const __half* ag = agp + (c + 1) * PCHUNK;
            const __half* bg = bgp + (c + 1) * PCHUNK;
            av0 = __ldg((const uint4*)(ag));
            av1 = __ldg((const uint4*)(ag + 8));
            bv0 = __ldg((const uint4*)(bg));
            bv1 = __ldg((const uint4*)(bg + 8));
        }

        uint32_t abuf = a_base + cur * bufA;
        uint32_t bbuf = b_base + cur * bufA;
#pragma unroll
        for (int kb = 0; kb < PCHUNK; kb += 16) {
            uint32_t a[4][4];
            uint32_t b[2][4];
#pragma unroll
            for (int i = 0; i < 4; i++)
                ldsm4(a[i][0], a[i][1], a[i][2], a[i][3],
                      abuf + ((a_row + i * 16) * PSTRIDE + kb + a_col) * 2);
#pragma unroll
            for (int j = 0; j < 2; j++)
                ldsm4(b[j][0], b[j][1], b[j][2], b[j][3],
                      bbuf + ((b_row + j * 16) * PSTRIDE + kb + b_col) * 2);
#pragma unroll
            for (int i = 0; i < 4; i++) {
#pragma unroll
                for (int j = 0; j < 2; j++) {
                    mma16816(acc[i][j * 2],     a[i], b[j][0], b[j][1]);
                    mma16816(acc[i][j * 2 + 1], a[i], b[j][2], b[j][3]);
                }
            }
        }
        __syncthreads();
        if (c + 1 < NCHUNK) {
            const int nxt = cur ^ 1;
            *(uint4*)&As[nxt][ssoff]     = av0;
            *(uint4*)&As[nxt][ssoff + 8] = av1;
            *(uint4*)&Bs[nxt][ssoff]     = bv0;
            *(uint4*)&Bs[nxt][ssoff + 8] = bv1;
            __syncthreads();
        }
    }

#pragma unroll
    for (int i = 0; i < 4; i++) {
        int row = m0 + wm * 64 + i * 16 + (lane >> 2);
#pragma unroll
        for (int jj = 0; jj < 4; jj++) {
            int col = n0 + wn * 32 + jj * 8 + (lane & 3) * 2;
            float2 bo = *(const float2*)&bout[col];
            float2 v0 = make_float2(acc[i][jj][0] + bo.x, acc[i][jj][1] + bo.y);
            float2 v1 = make_float2(acc[i][jj][2] + bo.x, acc[i][jj][3] + bo.y);
            *(float2*)&out[(size_t)row * NOUT + col] = v0;
            *(float2*)&out[(size_t)(row + 8) * NOUT + col] = v1;
        }
    }
}

// ---------------------------------------------------------------------------
extern "C" void kernel_launch(void* const* d_in, const int* in_sizes, int n_in,
                              void* d_out, int out_size)
{
    const int*   x     = (const int*)  d_in[0];
    const float* emb   = (const float*)d_in[2];
    const float* Wih_f = (const float*)d_in[3];
    const float* Whh_f = (const float*)d_in[4];
    const float* bih_f = (const float*)d_in[5];
    const float* bhh_f = (const float*)d_in[6];
    const float* Wih_b = (const float*)d_in[7];
    const float* Whh_b = (const float*)d_in[8];
    const float* bih_b = (const float*)d_in[9];
    const float* bhh_b = (const float*)d_in[10];
    const float* Wout  = (const float*)d_in[11];
    const float* bout  = (const float*)d_in[12];
    float* out = (float*)d_out;

    float *Xf_p, *Xb_p;
    cudaGetSymbolAddress((void**)&Xf_p, g_Xf);
    cudaGetSymbolAddress((void**)&Xb_p, g_Xb);

    dim3 blk(256);

    wout_split_kernel<<<NOUT, blk>>>(Wout);
    whh_split_kernel<<<dim3(2048, 2), blk>>>(Whh_f, Whh_b);

    xgemm_kernel<<<dim3(16, 4, 2), blk>>>(emb, x, Wih_f, Wih_b,
                                          bih_f, bhh_f, bih_b, bhh_b,
                                          Xf_p, Xb_p);

    for (int s = 0; s < 32; s++) {
        dim3 grid(32, (8 * (s + 1) + 63) / 64, 2);
        lstm_step_kernel<<<grid, blk>>>(Xf_p, Xb_p, s);
    }

    mean_split_kernel<<<dim3(496, 8), blk>>>();

    proj_mma_kernel<<<dim3(60, 31), blk>>>(bout, out);
}